// round 12
// baseline (speedup 1.0000x reference)
#include <cuda_runtime.h>
#include <cstdint>
#include <math.h>

#define TOK 16384
#define N1  8448

// ---------- static device scratch ----------
__device__ float  g_emb[4 * 1536];
__device__ int8_t g_xq1[TOK * 768];
__device__ float  g_ri1[TOK];
__device__ int8_t g_wcat[N1 * 768];
__device__ int8_t g_wqo[768 * 768];
__device__ int8_t g_wqd[768 * 3072];
__device__ int8_t g_wqp[768 * 1536];
__device__ float  g_cs1[N1];
__device__ float  g_cso[768];
__device__ float  g_csd[768];
__device__ float  g_csp[768];
__device__ double g_part[7 * 256];
__device__ float  g_Cm[(size_t)TOK * 3072];   // m = silu(gm)*y
__device__ float  g_fg[TOK * 768];            // sigmoid(f)
__device__ float  g_ig[TOK * 768];            // u = silu(i)*(1-f)
__device__ float  g_sg[TOK * 768];            // silu(g)
__device__ float  g_og[TOK * 768];
__device__ float  g_S[4 * 128 * 768];
__device__ float  g_P[4 * 128 * 768];
__device__ float  g_Cy[4 * 128 * 768];
__device__ int8_t g_xq2[TOK * 768];
__device__ float  g_ri2[TOK];
__device__ int8_t g_xq3[(size_t)TOK * 3072];
__device__ float  g_ri3[TOK];
__device__ int8_t g_xq4[(size_t)TOK * 1536];
__device__ float  g_ri4[TOK];
__device__ float  g_cattn[TOK * 768];
__device__ float  g_cmlp[TOK * 768];

// ---------- helpers ----------
__device__ __forceinline__ float siluf(float x) { return x / (1.f + expf(-x)); }
__device__ __forceinline__ float sigmf(float x) { return 1.f / (1.f + expf(-x)); }

__device__ __forceinline__ float blkSum(float v, float* sh) {
    int t = threadIdx.x;
    sh[t] = v; __syncthreads();
    #pragma unroll
    for (int s = 128; s > 0; s >>= 1) { if (t < s) sh[t] += sh[t + s]; __syncthreads(); }
    float r = sh[0]; __syncthreads();
    return r;
}
__device__ __forceinline__ float blkMax(float v, float* sh) {
    int t = threadIdx.x;
    sh[t] = v; __syncthreads();
    #pragma unroll
    for (int s = 128; s > 0; s >>= 1) { if (t < s) sh[t] = fmaxf(sh[t], sh[t + s]); __syncthreads(); }
    float r = sh[0]; __syncthreads();
    return r;
}
__device__ __forceinline__ int8_t q8(float v, float qs) {
    float q = rintf(v * qs);
    return (int8_t)fminf(fmaxf(q, -128.f), 127.f);
}

__device__ __constant__ int c_wn[7] = {589824, 589824, 589824, 4718592, 589824, 2359296, 1179648};

__device__ __forceinline__ const float* pick_w(int id, const float* w0, const float* w1,
    const float* w2, const float* w3, const float* w4, const float* w5, const float* w6) {
    switch (id) { case 0: return w0; case 1: return w1; case 2: return w2; case 3: return w3;
                  case 4: return w4; case 5: return w5; default: return w6; }
}

// ---------- launch 1: weight |w| partial sums (y=0..6) + AdaLN emb (y=7) ----------
__global__ void wabs_emb(const float* w0, const float* w1, const float* w2, const float* w3,
                         const float* w4, const float* w5, const float* w6,
                         const float* __restrict__ c, const float* __restrict__ w_emb,
                         const float* __restrict__ b_emb) {
    int id = blockIdx.y;
    int tid = threadIdx.x;
    if (id == 7) {
        if (blockIdx.x >= 6) return;
        __shared__ float sc[3072];
        for (int idx = tid; idx < 3072; idx += 256) sc[idx] = siluf(c[idx]);
        __syncthreads();
        int n = blockIdx.x * 256 + tid;   // 0..1535
        const float* wr = w_emb + (size_t)n * 768;
        float a0 = b_emb[n], a1 = a0, a2 = a0, a3 = a0;
        for (int k = 0; k < 768; ++k) {
            float wv = wr[k];
            a0 += sc[k] * wv; a1 += sc[768 + k] * wv;
            a2 += sc[1536 + k] * wv; a3 += sc[2304 + k] * wv;
        }
        g_emb[n] = a0; g_emb[1536 + n] = a1; g_emb[3072 + n] = a2; g_emb[4608 + n] = a3;
        return;
    }
    const float* w = pick_w(id, w0, w1, w2, w3, w4, w5, w6);
    int n = c_wn[id];
    __shared__ double sh[256];
    double s = 0.0;
    for (int i = blockIdx.x * 256 + tid; i < n; i += 65536) s += (double)fabsf(w[i]);
    sh[tid] = s; __syncthreads();
    #pragma unroll
    for (int k = 128; k > 0; k >>= 1) { if (tid < k) sh[tid] += sh[tid + k]; __syncthreads(); }
    if (tid == 0) g_part[id * 256 + blockIdx.x] = sh[0];
}

// ---------- launch 2: quantize weights (interleaved layout) + colinv arrays ----------
__global__ void wquant_all(const float* w0, const float* w1, const float* w2, const float* w3,
                           const float* w4, const float* w5, const float* w6) {
    int id = blockIdx.y;
    int tid = threadIdx.x;
    const float* w = pick_w(id, w0, w1, w2, w3, w4, w5, w6);
    int n = c_wn[id];

    __shared__ double sh[256];
    __shared__ float tscs;
    sh[tid] = g_part[id * 256 + tid]; __syncthreads();
    #pragma unroll
    for (int k = 128; k > 0; k >>= 1) { if (tid < k) sh[tid] += sh[tid + k]; __syncthreads(); }
    if (tid == 0) tscs = fmaxf((float)(sh[0] / (double)n), 1e-5f);
    __syncthreads();
    float s = 1.0f / tscs;

    for (int i = blockIdx.x * 256 + tid; i < n; i += 65536) {
        float q = rintf(w[i] * s);
        int8_t qv = (int8_t)fminf(fmaxf(q, -1.f), 1.f);
        int r = i / 768, k = i % 768;
        if (id == 0)      g_wcat[(size_t)(2 * r) * 768 + k] = qv;
        else if (id == 1) g_wcat[(size_t)(2 * r + 1) * 768 + k] = qv;
        else if (id == 2) g_wcat[(size_t)(1536 + r) * 768 + k] = qv;
        else if (id == 3) {
            int dr = (r < 3072) ? (2304 + 2 * r) : (2305 + 2 * (r - 3072));
            g_wcat[(size_t)dr * 768 + k] = qv;
        }
        else if (id == 4) g_wqo[i] = qv;
        else if (id == 5) g_wqd[i] = qv;
        else              g_wqp[i] = qv;
    }

    if (id == 6 && blockIdx.x == 0) {
        __shared__ float tv[7];
        for (int j = 0; j < 7; j++) {
            sh[tid] = g_part[j * 256 + tid]; __syncthreads();
            #pragma unroll
            for (int k = 128; k > 0; k >>= 1) { if (tid < k) sh[tid] += sh[tid + k]; __syncthreads(); }
            if (tid == 0) tv[j] = fmaxf((float)(sh[0] / (double)c_wn[j]), 1e-5f);
            __syncthreads();
        }
        for (int j = tid; j < N1; j += 256) {
            float v;
            if (j < 1536)      v = (j & 1) ? tv[1] : tv[0];
            else if (j < 2304) v = tv[2];
            else               v = tv[3];
            g_cs1[j] = v;
        }
        for (int j = tid; j < 768; j += 256) {
            g_cso[j] = tv[4]; g_csd[j] = tv[5]; g_csp[j] = tv[6];
        }
    }
}

// ---------- launch 3: LN -> adaLN scale -> RMS -> int8 quant ----------
__global__ void norm1_quant(const float* __restrict__ x) {
    __shared__ float sh[256];
    int tok = blockIdx.x, b = tok >> 12, tid = threadIdx.x;
    const float* xr = x + (size_t)tok * 768;
    float v0 = xr[tid], v1 = xr[tid + 256], v2 = xr[tid + 512];
    float mu = blkSum(v0 + v1 + v2, sh) * (1.f / 768.f);
    float d0 = v0 - mu, d1 = v1 - mu, d2 = v2 - mu;
    float var = blkSum(d0 * d0 + d1 * d1 + d2 * d2, sh) * (1.f / 768.f);
    float r1 = 1.f / sqrtf(var + 1e-6f);
    const float* eb = g_emb + b * 1536;
    float n0 = d0 * r1 * (1.f + eb[tid]);
    float n1 = d1 * r1 * (1.f + eb[tid + 256]);
    float n2 = d2 * r1 * (1.f + eb[tid + 512]);
    float ms = blkSum(n0 * n0 + n1 * n1 + n2 * n2, sh) * (1.f / 768.f);
    float r2 = 1.f / sqrtf(ms + 1e-6f);
    n0 *= r2; n1 *= r2; n2 *= r2;
    float am = blkMax(fmaxf(fabsf(n0), fmaxf(fabsf(n1), fabsf(n2))), sh);
    am = fmaxf(am, 1e-5f);
    float qs = 127.f / am;
    size_t base = (size_t)tok * 768;
    g_xq1[base + tid] = q8(n0, qs);
    g_xq1[base + tid + 256] = q8(n1, qs);
    g_xq1[base + tid + 512] = q8(n2, qs);
    if (tid == 0) g_ri1[tok] = am * (1.f / 127.f);
}

// ---------- int8 tensor-core GEMM: 128x128 block, 512 threads, 32x32 warp tile ----------
// K-chunk 128 (144B-padded rows), 3-stage ring, fully unrolled stage indices.
__device__ __forceinline__ void ldsm4(uint32_t* r, uint32_t addr) {
    asm volatile("ldmatrix.sync.aligned.m8n8.x4.shared.b16 {%0,%1,%2,%3}, [%4];\n"
                 : "=r"(r[0]), "=r"(r[1]), "=r"(r[2]), "=r"(r[3]) : "r"(addr));
}
__device__ __forceinline__ void mma_s8(int* c, const uint32_t* a, uint32_t b0, uint32_t b1) {
    asm volatile(
        "mma.sync.aligned.m16n8k32.row.col.s32.s8.s8.s32 "
        "{%0,%1,%2,%3}, {%4,%5,%6,%7}, {%8,%9}, {%0,%1,%2,%3};\n"
        : "+r"(c[0]), "+r"(c[1]), "+r"(c[2]), "+r"(c[3])
        : "r"(a[0]), "r"(a[1]), "r"(a[2]), "r"(a[3]), "r"(b0), "r"(b1));
}
__device__ __forceinline__ void cp16(uint32_t d, const int8_t* s) {
    asm volatile("cp.async.cg.shared.global [%0],[%1],16;\n" :: "r"(d), "l"(s) : "memory");
}

#define A_ST   18432                 // 128 rows * 144B
#define STAGE_BYTES 36864            // A + B
#define NSTG   3

__global__ __launch_bounds__(512, 2)
void gemm_s8(int id, int ldN, int K, const float* __restrict__ xres,
             const float* __restrict__ bias, float* __restrict__ outp) {
    const int8_t* A; const int8_t* Bm; float* C; const float* ri; const float* ci; int mode = 0;
    if (id == 1)      { A = g_xq1; Bm = g_wcat; C = nullptr;  ri = g_ri1; ci = g_cs1; mode = 2; }
    else if (id == 2) { A = g_xq2; Bm = g_wqo;  C = g_cattn;  ri = g_ri2; ci = g_cso; }
    else if (id == 3) { A = g_xq3; Bm = g_wqd;  C = g_cmlp;   ri = g_ri3; ci = g_csd; }
    else              { A = g_xq4; Bm = g_wqp;  C = outp;     ri = g_ri4; ci = g_csp; mode = 1; }

    extern __shared__ int8_t sm[];
    int tid = threadIdx.x, lane = tid & 31, wid = tid >> 5;
    int wm = wid >> 2, wn = wid & 3;           // 4x4 warp grid, warp tile 32x32
    int bm0 = blockIdx.y * 128, bn0 = blockIdx.x * 128;

    // loaders: 4 thr/row x 32B, 128 rows each operand
    const int8_t* gA = A + (size_t)(bm0 + (tid >> 2)) * K + (tid & 3) * 32;
    const int8_t* gB = Bm + (size_t)(bn0 + (tid >> 2)) * K + (tid & 3) * 32;
    uint32_t s0 = (uint32_t)__cvta_generic_to_shared(sm);
    uint32_t wo = (uint32_t)(tid >> 2) * 144 + (tid & 3) * 32;

    int acc[2][4][4];
    #pragma unroll
    for (int a = 0; a < 2; a++)
        #pragma unroll
        for (int b = 0; b < 4; b++)
            #pragma unroll
            for (int r = 0; r < 4; r++) acc[a][b][r] = 0;

    const int KT = K >> 7;   // chunks of 128; KT in {6, 24, 12} -> all multiples of 3

    #pragma unroll
    for (int p = 0; p < 2; p++) {
        uint32_t sb = s0 + p * STAGE_BYTES;
        const int8_t* pa = gA + p * 128;
        const int8_t* pb = gB + p * 128;
        cp16(sb + wo, pa); cp16(sb + wo + 16, pa + 16);
        cp16(sb + A_ST + wo, pb); cp16(sb + A_ST + wo + 16, pb + 16);
        asm volatile("cp.async.commit_group;\n" ::: "memory");
    }

    uint32_t aOff = (uint32_t)(wm * 32 + (lane & 15)) * 144 + ((lane >> 4) << 4);
    uint32_t bOff = A_ST + (uint32_t)(wn * 32 + (lane & 15)) * 144 + ((lane >> 4) << 4);

    for (int kt0 = 0; kt0 < KT; kt0 += 3) {
        #pragma unroll
        for (int s = 0; s < 3; s++) {
            int kt = kt0 + s;                  // stage index == s (kt0 multiple of 3)
            if (kt < KT - 1) asm volatile("cp.async.wait_group 1;\n" ::: "memory");
            else             asm volatile("cp.async.wait_group 0;\n" ::: "memory");
            __syncthreads();
            if (kt + 2 < KT) {
                uint32_t sb = s0 + (uint32_t)(((s + 2) % 3) * STAGE_BYTES);
                const int8_t* pa = gA + (kt + 2) * 128;
                const int8_t* pb = gB + (kt + 2) * 128;
                cp16(sb + wo, pa); cp16(sb + wo + 16, pa + 16);
                cp16(sb + A_ST + wo, pb); cp16(sb + A_ST + wo + 16, pb + 16);
                asm volatile("cp.async.commit_group;\n" ::: "memory");
            }
            uint32_t aT = s0 + (uint32_t)(s * STAGE_BYTES) + aOff;
            uint32_t bT = s0 + (uint32_t)(s * STAGE_BYTES) + bOff;
            #pragma unroll
            for (int ks = 0; ks < 128; ks += 32) {
                uint32_t af[2][4], bf[2][4];
                ldsm4(af[0], aT + ks);
                ldsm4(af[1], aT + 16 * 144 + ks);
                ldsm4(bf[0], bT + ks);
                ldsm4(bf[1], bT + 16 * 144 + ks);
                #pragma unroll
                for (int fm = 0; fm < 2; ++fm)
                    #pragma unroll
                    for (int fn = 0; fn < 4; ++fn)
                        mma_s8(acc[fm][fn], af[fm], bf[fn >> 1][fn & 1], bf[fn >> 1][(fn & 1) + 2]);
            }
        }
    }

    // epilogue
    int g = lane >> 2, tg = lane & 3;
    #pragma unroll
    for (int fm = 0; fm < 2; ++fm) {
        int r0 = bm0 + wm * 32 + fm * 16 + g;
        int r1 = r0 + 8;
        float ri0 = ri[r0], ri1 = ri[r1];
        #pragma unroll
        for (int fn = 0; fn < 4; ++fn) {
            int cc = bn0 + wn * 32 + fn * 8 + tg * 2;
            float cv0 = ci[cc], cv1 = ci[cc + 1];
            float v00 = (float)acc[fm][fn][0] * ri0 * cv0;
            float v01 = (float)acc[fm][fn][1] * ri0 * cv1;
            float v10 = (float)acc[fm][fn][2] * ri1 * cv0;
            float v11 = (float)acc[fm][fn][3] * ri1 * cv1;
            if (mode == 2) {
                if (cc < 1536) {                       // (i,f) pair -> u, f
                    int j = cc >> 1;
                    float f0 = sigmf(v01), f1 = sigmf(v11);
                    g_ig[(size_t)r0 * 768 + j] = siluf(v00) * (1.f - f0);
                    g_ig[(size_t)r1 * 768 + j] = siluf(v10) * (1.f - f1);
                    g_fg[(size_t)r0 * 768 + j] = f0;
                    g_fg[(size_t)r1 * 768 + j] = f1;
                } else if (cc < 2304) {                // g -> silu(g)
                    int j = cc - 1536;
                    g_sg[(size_t)r0 * 768 + j] = siluf(v00);
                    g_sg[(size_t)r0 * 768 + j + 1] = siluf(v01);
                    g_sg[(size_t)r1 * 768 + j] = siluf(v10);
                    g_sg[(size_t)r1 * 768 + j + 1] = siluf(v11);
                } else {                               // (gm,y) pair -> m
                    int j = (cc - 2304) >> 1;
                    g_Cm[(size_t)r0 * 3072 + j] = siluf(v00) * v01;
                    g_Cm[(size_t)r1 * 3072 + j] = siluf(v10) * v11;
                }
            } else if (mode == 0) {
                C[(size_t)r0 * ldN + cc] = v00; C[(size_t)r0 * ldN + cc + 1] = v01;
                C[(size_t)r1 * ldN + cc] = v10; C[(size_t)r1 * ldN + cc + 1] = v11;
            } else {
                int b0 = r0 >> 12, b1 = r1 >> 12;
                float gt00 = g_emb[b0 * 1536 + 768 + cc], gt01 = g_emb[b0 * 1536 + 768 + cc + 1];
                float gt10 = g_emb[b1 * 1536 + 768 + cc], gt11 = g_emb[b1 * 1536 + 768 + cc + 1];
                size_t o00 = (size_t)r0 * 768 + cc, o10 = (size_t)r1 * 768 + cc;
                C[o00]     = xres[o00]     + gt00 * (v00 + bias[cc]);
                C[o00 + 1] = xres[o00 + 1] + gt01 * (v01 + bias[cc + 1]);
                C[o10]     = xres[o10]     + gt10 * (v10 + bias[cc]);
                C[o10 + 1] = xres[o10 + 1] + gt11 * (v11 + bias[cc + 1]);
            }
        }
    }
}

// ---------- chunked scan (u already includes (1-f)) ----------
__global__ void scan1() {
    int d = blockIdx.x * 256 + threadIdx.x;
    int c = blockIdx.y, b = blockIdx.z;
    size_t base = ((size_t)(b * 4096 + c * 32)) * 768 + d;
    float h = 0.f, P = 1.f;
    #pragma unroll 8
    for (int t = 0; t < 32; t++) {
        size_t k = base + (size_t)t * 768;
        float f = g_fg[k];
        h = f * h + g_ig[k];
        P *= f;
    }
    size_t idx = (size_t)(b * 128 + c) * 768 + d;
    g_S[idx] = h; g_P[idx] = P;
}
__global__ void scan2() {
    int i = blockIdx.x * 256 + threadIdx.x;
    int b = i / 768, d = i % 768;
    float carry = 0.f;
    for (int cc = 0; cc < 128; cc++) {
        size_t idx = (size_t)(b * 128 + cc) * 768 + d;
        g_Cy[idx] = carry;
        carry = g_P[idx] * carry + g_S[idx];
    }
}
__global__ void scan3() {
    int d = blockIdx.x * 256 + threadIdx.x;
    int c = blockIdx.y, b = blockIdx.z;
    size_t base = ((size_t)(b * 4096 + c * 32)) * 768 + d;
    float h = g_Cy[(size_t)(b * 128 + c) * 768 + d];
    #pragma unroll 8
    for (int t = 0; t < 32; t++) {
        size_t k = base + (size_t)t * 768;
        h = g_fg[k] * h + g_ig[k];
        g_og[k] = h;
    }
}

// ---------- RMS(o)*w_gn*silu(g) -> RMS -> quant ----------
__global__ void norm2_quant(const float* __restrict__ w_gn) {
    __shared__ float sh[256];
    int tok = blockIdx.x, tid = threadIdx.x;
    size_t base = (size_t)tok * 768;
    float o0 = g_og[base + tid], o1 = g_og[base + tid + 256], o2 = g_og[base + tid + 512];
    float ms = blkSum(o0 * o0 + o1 * o1 + o2 * o2, sh) * (1.f / 768.f);
    float r1 = 1.f / sqrtf(ms + 1e-6f);
    float v0 = o0 * r1 * w_gn[tid]       * g_sg[base + tid];
    float v1 = o1 * r1 * w_gn[tid + 256] * g_sg[base + tid + 256];
    float v2 = o2 * r1 * w_gn[tid + 512] * g_sg[base + tid + 512];
    float ms2 = blkSum(v0 * v0 + v1 * v1 + v2 * v2, sh) * (1.f / 768.f);
    float r2 = 1.f / sqrtf(ms2 + 1e-6f);
    v0 *= r2; v1 *= r2; v2 *= r2;
    float am = blkMax(fmaxf(fabsf(v0), fmaxf(fabsf(v1), fabsf(v2))), sh);
    am = fmaxf(am, 1e-5f);
    float qs = 127.f / am;
    g_xq2[base + tid] = q8(v0, qs);
    g_xq2[base + tid + 256] = q8(v1, qs);
    g_xq2[base + tid + 512] = q8(v2, qs);
    if (tid == 0) g_ri2[tok] = am * (1.f / 127.f);
}

// ---------- MLP branch: RMS -> quant ----------
__global__ void mlp_nq() {
    __shared__ float sh[256];
    int tok = blockIdx.x, tid = threadIdx.x;
    const float* row = g_Cm + (size_t)tok * 3072;
    float mv[12], ss = 0.f;
    #pragma unroll
    for (int k = 0; k < 12; k++) {
        float m = row[tid + k * 256];
        mv[k] = m; ss += m * m;
    }
    float ms = blkSum(ss, sh) * (1.f / 3072.f);
    float r = 1.f / sqrtf(ms + 1e-6f);
    float am = 0.f;
    #pragma unroll
    for (int k = 0; k < 12; k++) am = fmaxf(am, fabsf(mv[k]));
    am = blkMax(am, sh) * r;
    am = fmaxf(am, 1e-5f);
    float qs = 127.f / am;
    size_t base = (size_t)tok * 3072;
    #pragma unroll
    for (int k = 0; k < 12; k++) g_xq3[base + tid + k * 256] = q8(mv[k] * r, qs);
    if (tid == 0) g_ri3[tok] = am * (1.f / 127.f);
}

// ---------- concat -> RMS -> quant ----------
__global__ void cat_nq() {
    __shared__ float sh[256];
    int tok = blockIdx.x, tid = threadIdx.x;
    float mv[6], ss = 0.f;
    #pragma unroll
    for (int k = 0; k < 6; k++) {
        int j = tid + k * 256;
        float v = (k < 3) ? g_cattn[(size_t)tok * 768 + j] : g_cmlp[(size_t)tok * 768 + j - 768];
        mv[k] = v; ss += v * v;
    }
    float ms = blkSum(ss, sh) * (1.f / 1536.f);
    float r = 1.f / sqrtf(ms + 1e-6f);
    float am = 0.f;
    #pragma unroll
    for (int k = 0; k < 6; k++) am = fmaxf(am, fabsf(mv[k]));
    am = blkMax(am, sh) * r;
    am = fmaxf(am, 1e-5f);
    float qs = 127.f / am;
    size_t base = (size_t)tok * 1536;
    #pragma unroll
    for (int k = 0; k < 6; k++) g_xq4[base + tid + k * 256] = q8(mv[k] * r, qs);
    if (tid == 0) g_ri4[tok] = am * (1.f / 127.f);
}

// ---------- launch ----------
extern "C" void kernel_launch(void* const* d_in, const int* in_sizes, int n_in,
                              void* d_out, int out_size) {
    const float* x      = (const float*)d_in[0];
    const float* c      = (const float*)d_in[1];
    const float* w_emb  = (const float*)d_in[2];
    const float* b_emb  = (const float*)d_in[3];
    const float* w_i    = (const float*)d_in[4];
    const float* w_f    = (const float*)d_in[5];
    const float* w_g    = (const float*)d_in[6];
    const float* w_gn   = (const float*)d_in[7];
    const float* w_o    = (const float*)d_in[8];
    const float* w_gate = (const float*)d_in[9];
    const float* w_down = (const float*)d_in[10];
    const float* w_proj = (const float*)d_in[11];
    const float* b_proj = (const float*)d_in[12];
    float* out = (float*)d_out;

    const int GSMEM = NSTG * STAGE_BYTES;   // 110592
    cudaFuncSetAttribute(gemm_s8, cudaFuncAttributeMaxDynamicSharedMemorySize, GSMEM);

    wabs_emb<<<dim3(256, 8), 256>>>(w_i, w_f, w_g, w_gate, w_o, w_down, w_proj,
                                    c, w_emb, b_emb);                               // 1
    wquant_all<<<dim3(256, 7), 256>>>(w_i, w_f, w_g, w_gate, w_o, w_down, w_proj);  // 2
    norm1_quant<<<16384, 256>>>(x);                                                 // 3
    gemm_s8<<<dim3(66, 128), 512, GSMEM>>>(1, N1, 768, nullptr, nullptr, nullptr);  // 4 <- ncu
    scan1<<<dim3(3, 128, 4), 256>>>();
    scan2<<<12, 256>>>();
    scan3<<<dim3(3, 128, 4), 256>>>();
    norm2_quant<<<16384, 256>>>(w_gn);
    gemm_s8<<<dim3(6, 128), 512, GSMEM>>>(2, 768, 768, nullptr, nullptr, nullptr);
    mlp_nq<<<16384, 256>>>();
    gemm_s8<<<dim3(6, 128), 512, GSMEM>>>(3, 768, 3072, nullptr, nullptr, nullptr);
    cat_nq<<<16384, 256>>>();
    gemm_s8<<<dim3(6, 128), 512, GSMEM>>>(4, 768, 1536, x, b_proj, out);
}

// round 14
// speedup vs baseline: 1.0840x; 1.0840x over previous
#include <cuda_runtime.h>
#include <cstdint>
#include <math.h>

#define TOK 16384
#define N1  8448

// ---------- static device scratch ----------
__device__ float  g_emb[4 * 1536];
__device__ int8_t g_xq1[TOK * 768];
__device__ float  g_ri1[TOK];
__device__ int8_t g_wcat[N1 * 768];
__device__ int8_t g_wqo[768 * 768];
__device__ int8_t g_wqd[768 * 3072];
__device__ int8_t g_wqp[768 * 1536];
__device__ float  g_cs1[N1];
__device__ float  g_cso[768];
__device__ float  g_csd[768];
__device__ float  g_csp[768];
__device__ double g_part[7 * 256];
__device__ float  g_Cm[(size_t)TOK * 3072];   // m = silu(gm)*y
__device__ float  g_fg[TOK * 768];            // sigmoid(f)
__device__ float  g_ig[TOK * 768];            // u = silu(i)*(1-f)
__device__ float  g_sg[TOK * 768];            // silu(g)
__device__ float  g_og[TOK * 768];
__device__ float  g_S[4 * 128 * 768];
__device__ float  g_P[4 * 128 * 768];
__device__ float  g_Cy[4 * 128 * 768];
__device__ int8_t g_xq2[TOK * 768];
__device__ float  g_ri2[TOK];
__device__ int8_t g_xq3[(size_t)TOK * 3072];
__device__ float  g_ri3[TOK];
__device__ int8_t g_xq4[(size_t)TOK * 1536];
__device__ float  g_ri4[TOK];
__device__ float  g_cattn[TOK * 768];
__device__ float  g_cmlp[TOK * 768];

// ---------- helpers ----------
__device__ __forceinline__ float siluf(float x) { return x / (1.f + expf(-x)); }
__device__ __forceinline__ float sigmf(float x) { return 1.f / (1.f + expf(-x)); }

// shuffle-based block reductions (256 threads = 8 warps); 2 barriers each
__device__ __forceinline__ float blkSum(float v, float* sh) {
    int lane = threadIdx.x & 31, w = threadIdx.x >> 5;
    #pragma unroll
    for (int o = 16; o > 0; o >>= 1) v += __shfl_xor_sync(0xffffffffu, v, o);
    if (lane == 0) sh[w] = v;
    __syncthreads();
    float r = sh[0];
    #pragma unroll
    for (int i = 1; i < 8; i++) r += sh[i];
    __syncthreads();
    return r;
}
__device__ __forceinline__ float blkMax(float v, float* sh) {
    int lane = threadIdx.x & 31, w = threadIdx.x >> 5;
    #pragma unroll
    for (int o = 16; o > 0; o >>= 1) v = fmaxf(v, __shfl_xor_sync(0xffffffffu, v, o));
    if (lane == 0) sh[w] = v;
    __syncthreads();
    float r = sh[0];
    #pragma unroll
    for (int i = 1; i < 8; i++) r = fmaxf(r, sh[i]);
    __syncthreads();
    return r;
}
__device__ __forceinline__ int8_t q8(float v, float qs) {
    float q = rintf(v * qs);
    return (int8_t)fminf(fmaxf(q, -128.f), 127.f);
}

__device__ __constant__ int c_wn[7] = {589824, 589824, 589824, 4718592, 589824, 2359296, 1179648};

__device__ __forceinline__ const float* pick_w(int id, const float* w0, const float* w1,
    const float* w2, const float* w3, const float* w4, const float* w5, const float* w6) {
    switch (id) { case 0: return w0; case 1: return w1; case 2: return w2; case 3: return w3;
                  case 4: return w4; case 5: return w5; default: return w6; }
}

// ---------- launch 1: weight |w| partial sums (y=0..6) + AdaLN emb (y=7) ----------
__global__ void wabs_emb(const float* w0, const float* w1, const float* w2, const float* w3,
                         const float* w4, const float* w5, const float* w6,
                         const float* __restrict__ c, const float* __restrict__ w_emb,
                         const float* __restrict__ b_emb) {
    int id = blockIdx.y;
    int tid = threadIdx.x;
    if (id == 7) {
        if (blockIdx.x >= 6) return;
        __shared__ float sc[3072];
        for (int idx = tid; idx < 3072; idx += 256) sc[idx] = siluf(c[idx]);
        __syncthreads();
        int n = blockIdx.x * 256 + tid;   // 0..1535
        const float* wr = w_emb + (size_t)n * 768;
        float a0 = b_emb[n], a1 = a0, a2 = a0, a3 = a0;
        for (int k = 0; k < 768; ++k) {
            float wv = wr[k];
            a0 += sc[k] * wv; a1 += sc[768 + k] * wv;
            a2 += sc[1536 + k] * wv; a3 += sc[2304 + k] * wv;
        }
        g_emb[n] = a0; g_emb[1536 + n] = a1; g_emb[3072 + n] = a2; g_emb[4608 + n] = a3;
        return;
    }
    const float* w = pick_w(id, w0, w1, w2, w3, w4, w5, w6);
    int n = c_wn[id];
    __shared__ double sh[256];
    double s = 0.0;
    for (int i = blockIdx.x * 256 + tid; i < n; i += 65536) s += (double)fabsf(w[i]);
    sh[tid] = s; __syncthreads();
    #pragma unroll
    for (int k = 128; k > 0; k >>= 1) { if (tid < k) sh[tid] += sh[tid + k]; __syncthreads(); }
    if (tid == 0) g_part[id * 256 + blockIdx.x] = sh[0];
}

// ---------- launch 2: quantize weights (interleaved layout) + colinv arrays ----------
__global__ void wquant_all(const float* w0, const float* w1, const float* w2, const float* w3,
                           const float* w4, const float* w5, const float* w6) {
    int id = blockIdx.y;
    int tid = threadIdx.x;
    const float* w = pick_w(id, w0, w1, w2, w3, w4, w5, w6);
    int n = c_wn[id];

    __shared__ double sh[256];
    __shared__ float tscs;
    sh[tid] = g_part[id * 256 + tid]; __syncthreads();
    #pragma unroll
    for (int k = 128; k > 0; k >>= 1) { if (tid < k) sh[tid] += sh[tid + k]; __syncthreads(); }
    if (tid == 0) tscs = fmaxf((float)(sh[0] / (double)n), 1e-5f);
    __syncthreads();
    float s = 1.0f / tscs;

    for (int i = blockIdx.x * 256 + tid; i < n; i += 65536) {
        float q = rintf(w[i] * s);
        int8_t qv = (int8_t)fminf(fmaxf(q, -1.f), 1.f);
        int r = i / 768, k = i % 768;
        if (id == 0)      g_wcat[(size_t)(2 * r) * 768 + k] = qv;
        else if (id == 1) g_wcat[(size_t)(2 * r + 1) * 768 + k] = qv;
        else if (id == 2) g_wcat[(size_t)(1536 + r) * 768 + k] = qv;
        else if (id == 3) {
            int dr = (r < 3072) ? (2304 + 2 * r) : (2305 + 2 * (r - 3072));
            g_wcat[(size_t)dr * 768 + k] = qv;
        }
        else if (id == 4) g_wqo[i] = qv;
        else if (id == 5) g_wqd[i] = qv;
        else              g_wqp[i] = qv;
    }

    if (id == 6 && blockIdx.x == 0) {
        __shared__ float tv[7];
        for (int j = 0; j < 7; j++) {
            sh[tid] = g_part[j * 256 + tid]; __syncthreads();
            #pragma unroll
            for (int k = 128; k > 0; k >>= 1) { if (tid < k) sh[tid] += sh[tid + k]; __syncthreads(); }
            if (tid == 0) tv[j] = fmaxf((float)(sh[0] / (double)c_wn[j]), 1e-5f);
            __syncthreads();
        }
        for (int j = tid; j < N1; j += 256) {
            float v;
            if (j < 1536)      v = (j & 1) ? tv[1] : tv[0];
            else if (j < 2304) v = tv[2];
            else               v = tv[3];
            g_cs1[j] = v;
        }
        for (int j = tid; j < 768; j += 256) {
            g_cso[j] = tv[4]; g_csd[j] = tv[5]; g_csp[j] = tv[6];
        }
    }
}

// ---------- launch 3: LN -> adaLN scale -> RMS -> int8 quant ----------
__global__ void norm1_quant(const float* __restrict__ x) {
    __shared__ float sh[8];
    int tok = blockIdx.x, b = tok >> 12, tid = threadIdx.x;
    const float* xr = x + (size_t)tok * 768;
    float v0 = xr[tid], v1 = xr[tid + 256], v2 = xr[tid + 512];
    float mu = blkSum(v0 + v1 + v2, sh) * (1.f / 768.f);
    float d0 = v0 - mu, d1 = v1 - mu, d2 = v2 - mu;
    float var = blkSum(d0 * d0 + d1 * d1 + d2 * d2, sh) * (1.f / 768.f);
    float r1 = 1.f / sqrtf(var + 1e-6f);
    const float* eb = g_emb + b * 1536;
    float n0 = d0 * r1 * (1.f + eb[tid]);
    float n1 = d1 * r1 * (1.f + eb[tid + 256]);
    float n2 = d2 * r1 * (1.f + eb[tid + 512]);
    float ms = blkSum(n0 * n0 + n1 * n1 + n2 * n2, sh) * (1.f / 768.f);
    float r2 = 1.f / sqrtf(ms + 1e-6f);
    n0 *= r2; n1 *= r2; n2 *= r2;
    float am = blkMax(fmaxf(fabsf(n0), fmaxf(fabsf(n1), fabsf(n2))), sh);
    am = fmaxf(am, 1e-5f);
    float qs = 127.f / am;
    size_t base = (size_t)tok * 768;
    g_xq1[base + tid] = q8(n0, qs);
    g_xq1[base + tid + 256] = q8(n1, qs);
    g_xq1[base + tid + 512] = q8(n2, qs);
    if (tid == 0) g_ri1[tok] = am * (1.f / 127.f);
}

// ---------- int8 tensor-core GEMM: 128x128 block, 512 threads, 32x32 warp tile ----------
__device__ __forceinline__ void ldsm4(uint32_t* r, uint32_t addr) {
    asm volatile("ldmatrix.sync.aligned.m8n8.x4.shared.b16 {%0,%1,%2,%3}, [%4];\n"
                 : "=r"(r[0]), "=r"(r[1]), "=r"(r[2]), "=r"(r[3]) : "r"(addr));
}
__device__ __forceinline__ void mma_s8(int* c, const uint32_t* a, uint32_t b0, uint32_t b1) {
    asm volatile(
        "mma.sync.aligned.m16n8k32.row.col.s32.s8.s8.s32 "
        "{%0,%1,%2,%3}, {%4,%5,%6,%7}, {%8,%9}, {%0,%1,%2,%3};\n"
        : "+r"(c[0]), "+r"(c[1]), "+r"(c[2]), "+r"(c[3])
        : "r"(a[0]), "r"(a[1]), "r"(a[2]), "r"(a[3]), "r"(b0), "r"(b1));
}
__device__ __forceinline__ void cp16(uint32_t d, const int8_t* s) {
    asm volatile("cp.async.cg.shared.global [%0],[%1],16;\n" :: "r"(d), "l"(s) : "memory");
}

#define A_ST   10240                 // 128 rows * 80B
#define STAGE_BYTES 20480            // A + B
#define NSTG   4

__global__ __launch_bounds__(512, 2)
void gemm_s8(int id, int ldN, int K, const float* __restrict__ xres,
             const float* __restrict__ bias, float* __restrict__ outp) {
    const int8_t* A; const int8_t* Bm; float* C; const float* ri; const float* ci; int mode = 0;
    if (id == 1)      { A = g_xq1; Bm = g_wcat; C = nullptr;  ri = g_ri1; ci = g_cs1; mode = 2; }
    else if (id == 2) { A = g_xq2; Bm = g_wqo;  C = g_cattn;  ri = g_ri2; ci = g_cso; }
    else if (id == 3) { A = g_xq3; Bm = g_wqd;  C = g_cmlp;   ri = g_ri3; ci = g_csd; }
    else              { A = g_xq4; Bm = g_wqp;  C = outp;     ri = g_ri4; ci = g_csp; mode = 1; }

    extern __shared__ int8_t sm[];
    int tid = threadIdx.x, lane = tid & 31, wid = tid >> 5;
    int wm = wid >> 2, wn = wid & 3;           // 4x4 warp grid, warp tile 32x32
    int bm0 = blockIdx.y * 128, bn0 = blockIdx.x * 128;

    // loaders: 4 thr/row x 16B, 128 rows each operand
    const int8_t* gA = A + (size_t)(bm0 + (tid >> 2)) * K + (tid & 3) * 16;
    const int8_t* gB = Bm + (size_t)(bn0 + (tid >> 2)) * K + (tid & 3) * 16;
    uint32_t s0 = (uint32_t)__cvta_generic_to_shared(sm);
    uint32_t wo = (uint32_t)(tid >> 2) * 80 + (tid & 3) * 16;

    int acc[2][4][4];
    #pragma unroll
    for (int a = 0; a < 2; a++)
        #pragma unroll
        for (int b = 0; b < 4; b++)
            #pragma unroll
            for (int r = 0; r < 4; r++) acc[a][b][r] = 0;

    const int KT = K >> 6;

    #pragma unroll
    for (int p = 0; p < 3; p++) {
        uint32_t sb = s0 + p * STAGE_BYTES;
        cp16(sb + wo, gA + p * 64);
        cp16(sb + A_ST + wo, gB + p * 64);
        asm volatile("cp.async.commit_group;\n" ::: "memory");
    }

    uint32_t aOff = (uint32_t)(wm * 32 + (lane & 15)) * 80 + ((lane >> 4) << 4);
    uint32_t bOff = A_ST + (uint32_t)(wn * 32 + (lane & 15)) * 80 + ((lane >> 4) << 4);

    uint32_t stR = 0, stW = 3 * STAGE_BYTES;
    for (int kt = 0; kt < KT; kt++) {
        int rem = KT - 1 - kt;
        if (rem >= 2)      asm volatile("cp.async.wait_group 2;\n" ::: "memory");
        else if (rem == 1) asm volatile("cp.async.wait_group 1;\n" ::: "memory");
        else               asm volatile("cp.async.wait_group 0;\n" ::: "memory");
        __syncthreads();
        if (kt + 3 < KT) {
            uint32_t sb = s0 + stW;
            cp16(sb + wo, gA + (kt + 3) * 64);
            cp16(sb + A_ST + wo, gB + (kt + 3) * 64);
            asm volatile("cp.async.commit_group;\n" ::: "memory");
            stW += STAGE_BYTES; if (stW == NSTG * STAGE_BYTES) stW = 0;
        }
        uint32_t aT = s0 + stR + aOff;
        uint32_t bT = s0 + stR + bOff;
        stR += STAGE_BYTES; if (stR == NSTG * STAGE_BYTES) stR = 0;
        #pragma unroll
        for (int ks = 0; ks < 64; ks += 32) {
            uint32_t af[2][4], bf[2][4];
            ldsm4(af[0], aT + ks);
            ldsm4(af[1], aT + 16 * 80 + ks);
            ldsm4(bf[0], bT + ks);
            ldsm4(bf[1], bT + 16 * 80 + ks);
            #pragma unroll
            for (int fm = 0; fm < 2; ++fm)
                #pragma unroll
                for (int fn = 0; fn < 4; ++fn)
                    mma_s8(acc[fm][fn], af[fm], bf[fn >> 1][fn & 1], bf[fn >> 1][(fn & 1) + 2]);
        }
    }

    // epilogue
    int g = lane >> 2, tg = lane & 3;
    #pragma unroll
    for (int fm = 0; fm < 2; ++fm) {
        int r0 = bm0 + wm * 32 + fm * 16 + g;
        int r1 = r0 + 8;
        float ri0 = ri[r0], ri1 = ri[r1];
        #pragma unroll
        for (int fn = 0; fn < 4; ++fn) {
            int cc = bn0 + wn * 32 + fn * 8 + tg * 2;
            float cv0 = ci[cc], cv1 = ci[cc + 1];
            float v00 = (float)acc[fm][fn][0] * ri0 * cv0;
            float v01 = (float)acc[fm][fn][1] * ri0 * cv1;
            float v10 = (float)acc[fm][fn][2] * ri1 * cv0;
            float v11 = (float)acc[fm][fn][3] * ri1 * cv1;
            if (mode == 2) {
                if (cc < 1536) {                       // (i,f) pair -> u, f
                    int j = cc >> 1;
                    float f0 = sigmf(v01), f1 = sigmf(v11);
                    g_ig[(size_t)r0 * 768 + j] = siluf(v00) * (1.f - f0);
                    g_ig[(size_t)r1 * 768 + j] = siluf(v10) * (1.f - f1);
                    g_fg[(size_t)r0 * 768 + j] = f0;
                    g_fg[(size_t)r1 * 768 + j] = f1;
                } else if (cc < 2304) {                // g -> silu(g)
                    int j = cc - 1536;
                    g_sg[(size_t)r0 * 768 + j] = siluf(v00);
                    g_sg[(size_t)r0 * 768 + j + 1] = siluf(v01);
                    g_sg[(size_t)r1 * 768 + j] = siluf(v10);
                    g_sg[(size_t)r1 * 768 + j + 1] = siluf(v11);
                } else {                               // (gm,y) pair -> m
                    int j = (cc - 2304) >> 1;
                    g_Cm[(size_t)r0 * 3072 + j] = siluf(v00) * v01;
                    g_Cm[(size_t)r1 * 3072 + j] = siluf(v10) * v11;
                }
            } else if (mode == 0) {
                C[(size_t)r0 * ldN + cc] = v00; C[(size_t)r0 * ldN + cc + 1] = v01;
                C[(size_t)r1 * ldN + cc] = v10; C[(size_t)r1 * ldN + cc + 1] = v11;
            } else {
                int b0 = r0 >> 12, b1 = r1 >> 12;
                float gt00 = g_emb[b0 * 1536 + 768 + cc], gt01 = g_emb[b0 * 1536 + 768 + cc + 1];
                float gt10 = g_emb[b1 * 1536 + 768 + cc], gt11 = g_emb[b1 * 1536 + 768 + cc + 1];
                size_t o00 = (size_t)r0 * 768 + cc, o10 = (size_t)r1 * 768 + cc;
                C[o00]     = xres[o00]     + gt00 * (v00 + bias[cc]);
                C[o00 + 1] = xres[o00 + 1] + gt01 * (v01 + bias[cc + 1]);
                C[o10]     = xres[o10]     + gt10 * (v10 + bias[cc]);
                C[o10 + 1] = xres[o10 + 1] + gt11 * (v11 + bias[cc + 1]);
            }
        }
    }
}

// ---------- chunked scan (u already includes (1-f)) ----------
__global__ void scan1() {
    int d = blockIdx.x * 256 + threadIdx.x;
    int c = blockIdx.y, b = blockIdx.z;
    size_t base = ((size_t)(b * 4096 + c * 32)) * 768 + d;
    float h = 0.f, P = 1.f;
    #pragma unroll 8
    for (int t = 0; t < 32; t++) {
        size_t k = base + (size_t)t * 768;
        float f = g_fg[k];
        h = f * h + g_ig[k];
        P *= f;
    }
    size_t idx = (size_t)(b * 128 + c) * 768 + d;
    g_S[idx] = h; g_P[idx] = P;
}
__global__ void scan2() {
    int i = blockIdx.x * 256 + threadIdx.x;
    int b = i / 768, d = i % 768;
    float carry = 0.f;
    for (int cc = 0; cc < 128; cc++) {
        size_t idx = (size_t)(b * 128 + cc) * 768 + d;
        g_Cy[idx] = carry;
        carry = g_P[idx] * carry + g_S[idx];
    }
}
__global__ void scan3() {
    int d = blockIdx.x * 256 + threadIdx.x;
    int c = blockIdx.y, b = blockIdx.z;
    size_t base = ((size_t)(b * 4096 + c * 32)) * 768 + d;
    float h = g_Cy[(size_t)(b * 128 + c) * 768 + d];
    #pragma unroll 8
    for (int t = 0; t < 32; t++) {
        size_t k = base + (size_t)t * 768;
        h = g_fg[k] * h + g_ig[k];
        g_og[k] = h;
    }
}

// ---------- RMS(o)*w_gn*silu(g) -> RMS -> quant ----------
__global__ void norm2_quant(const float* __restrict__ w_gn) {
    __shared__ float sh[8];
    int tok = blockIdx.x, tid = threadIdx.x;
    size_t base = (size_t)tok * 768;
    float o0 = g_og[base + tid], o1 = g_og[base + tid + 256], o2 = g_og[base + tid + 512];
    float ms = blkSum(o0 * o0 + o1 * o1 + o2 * o2, sh) * (1.f / 768.f);
    float r1 = 1.f / sqrtf(ms + 1e-6f);
    float v0 = o0 * r1 * w_gn[tid]       * g_sg[base + tid];
    float v1 = o1 * r1 * w_gn[tid + 256] * g_sg[base + tid + 256];
    float v2 = o2 * r1 * w_gn[tid + 512] * g_sg[base + tid + 512];
    float ms2 = blkSum(v0 * v0 + v1 * v1 + v2 * v2, sh) * (1.f / 768.f);
    float r2 = 1.f / sqrtf(ms2 + 1e-6f);
    v0 *= r2; v1 *= r2; v2 *= r2;
    float am = blkMax(fmaxf(fabsf(v0), fmaxf(fabsf(v1), fabsf(v2))), sh);
    am = fmaxf(am, 1e-5f);
    float qs = 127.f / am;
    g_xq2[base + tid] = q8(v0, qs);
    g_xq2[base + tid + 256] = q8(v1, qs);
    g_xq2[base + tid + 512] = q8(v2, qs);
    if (tid == 0) g_ri2[tok] = am * (1.f / 127.f);
}

// ---------- MLP branch: RMS -> quant ----------
__global__ void mlp_nq() {
    __shared__ float sh[8];
    int tok = blockIdx.x, tid = threadIdx.x;
    const float* row = g_Cm + (size_t)tok * 3072;
    float mv[12], ss = 0.f;
    #pragma unroll
    for (int k = 0; k < 12; k++) {
        float m = row[tid + k * 256];
        mv[k] = m; ss += m * m;
    }
    float ms = blkSum(ss, sh) * (1.f / 3072.f);
    float r = 1.f / sqrtf(ms + 1e-6f);
    float am = 0.f;
    #pragma unroll
    for (int k = 0; k < 12; k++) am = fmaxf(am, fabsf(mv[k]));
    am = blkMax(am, sh) * r;
    am = fmaxf(am, 1e-5f);
    float qs = 127.f / am;
    size_t base = (size_t)tok * 3072;
    #pragma unroll
    for (int k = 0; k < 12; k++) g_xq3[base + tid + k * 256] = q8(mv[k] * r, qs);
    if (tid == 0) g_ri3[tok] = am * (1.f / 127.f);
}

// ---------- concat -> RMS -> quant ----------
__global__ void cat_nq() {
    __shared__ float sh[8];
    int tok = blockIdx.x, tid = threadIdx.x;
    float mv[6], ss = 0.f;
    #pragma unroll
    for (int k = 0; k < 6; k++) {
        int j = tid + k * 256;
        float v = (k < 3) ? g_cattn[(size_t)tok * 768 + j] : g_cmlp[(size_t)tok * 768 + j - 768];
        mv[k] = v; ss += v * v;
    }
    float ms = blkSum(ss, sh) * (1.f / 1536.f);
    float r = 1.f / sqrtf(ms + 1e-6f);
    float am = 0.f;
    #pragma unroll
    for (int k = 0; k < 6; k++) am = fmaxf(am, fabsf(mv[k]));
    am = blkMax(am, sh) * r;
    am = fmaxf(am, 1e-5f);
    float qs = 127.f / am;
    size_t base = (size_t)tok * 1536;
    #pragma unroll
    for (int k = 0; k < 6; k++) g_xq4[base + tid + k * 256] = q8(mv[k] * r, qs);
    if (tid == 0) g_ri4[tok] = am * (1.f / 127.f);
}

// ---------- launch ----------
extern "C" void kernel_launch(void* const* d_in, const int* in_sizes, int n_in,
                              void* d_out, int out_size) {
    const float* x      = (const float*)d_in[0];
    const float* c      = (const float*)d_in[1];
    const float* w_emb  = (const float*)d_in[2];
    const float* b_emb  = (const float*)d_in[3];
    const float* w_i    = (const float*)d_in[4];
    const float* w_f    = (const float*)d_in[5];
    const float* w_g    = (const float*)d_in[6];
    const float* w_gn   = (const float*)d_in[7];
    const float* w_o    = (const float*)d_in[8];
    const float* w_gate = (const float*)d_in[9];
    const float* w_down = (const float*)d_in[10];
    const float* w_proj = (const float*)d_in[11];
    const float* b_proj = (const float*)d_in[12];
    float* out = (float*)d_out;

    const int GSMEM = NSTG * STAGE_BYTES;   // 81920
    cudaFuncSetAttribute(gemm_s8, cudaFuncAttributeMaxDynamicSharedMemorySize, GSMEM);

    wabs_emb<<<dim3(256, 8), 256>>>(w_i, w_f, w_g, w_gate, w_o, w_down, w_proj,
                                    c, w_emb, b_emb);                               // 1
    wquant_all<<<dim3(256, 7), 256>>>(w_i, w_f, w_g, w_gate, w_o, w_down, w_proj);  // 2
    norm1_quant<<<16384, 256>>>(x);                                                 // 3
    gemm_s8<<<dim3(66, 128), 512, GSMEM>>>(1, N1, 768, nullptr, nullptr, nullptr);  // 4 <- ncu
    scan1<<<dim3(3, 128, 4), 256>>>();
    scan2<<<12, 256>>>();
    scan3<<<dim3(3, 128, 4), 256>>>();
    norm2_quant<<<16384, 256>>>(w_gn);
    gemm_s8<<<dim3(6, 128), 512, GSMEM>>>(2, 768, 768, nullptr, nullptr, nullptr);
    mlp_nq<<<16384, 256>>>();
    gemm_s8<<<dim3(6, 128), 512, GSMEM>>>(3, 768, 3072, nullptr, nullptr, nullptr);
    cat_nq<<<16384, 256>>>();
    gemm_s8<<<dim3(6, 128), 512, GSMEM>>>(4, 768, 1536, x, b_proj, out);
}

// round 15
// speedup vs baseline: 1.0968x; 1.0118x over previous
#include <cuda_runtime.h>
#include <cstdint>
#include <math.h>

#define TOK 16384
#define N1  8448

// ---------- static device scratch ----------
__device__ float  g_emb[4 * 1536];
__device__ int8_t g_xq1[TOK * 768];
__device__ float  g_ri1[TOK];
__device__ int8_t g_wcat[N1 * 768];
__device__ int8_t g_wqo[768 * 768];
__device__ int8_t g_wqd[768 * 3072];
__device__ int8_t g_wqp[768 * 1536];
__device__ float  g_cs1[N1];
__device__ float  g_cso[768];
__device__ float  g_csd[768];
__device__ float  g_csp[768];
__device__ double g_part[7 * 256];
__device__ float  g_Cm[(size_t)TOK * 3072];   // m = silu(gm)*y
__device__ float  g_fg[TOK * 768];            // sigmoid(f)
__device__ float  g_ig[TOK * 768];            // u = silu(i)*(1-f)
__device__ float  g_sg[TOK * 768];            // silu(g)
__device__ float  g_og[TOK * 768];
__device__ float  g_S[4 * 128 * 768];
__device__ float  g_P[4 * 128 * 768];
__device__ float  g_Cy[4 * 128 * 768];
__device__ int8_t g_xq2[TOK * 768];
__device__ float  g_ri2[TOK];
__device__ int8_t g_xq3[(size_t)TOK * 3072];
__device__ float  g_ri3[TOK];
__device__ int8_t g_xq4[(size_t)TOK * 1536];
__device__ float  g_ri4[TOK];
__device__ float  g_cattn[TOK * 768];
__device__ float  g_cmlp[TOK * 768];

// ---------- helpers ----------
__device__ __forceinline__ float siluf(float x) { return x / (1.f + expf(-x)); }
__device__ __forceinline__ float sigmf(float x) { return 1.f / (1.f + expf(-x)); }

// shuffle-based block reductions (256 threads = 8 warps); 2 barriers each
__device__ __forceinline__ float blkSum(float v, float* sh) {
    int lane = threadIdx.x & 31, w = threadIdx.x >> 5;
    #pragma unroll
    for (int o = 16; o > 0; o >>= 1) v += __shfl_xor_sync(0xffffffffu, v, o);
    if (lane == 0) sh[w] = v;
    __syncthreads();
    float r = sh[0];
    #pragma unroll
    for (int i = 1; i < 8; i++) r += sh[i];
    __syncthreads();
    return r;
}
__device__ __forceinline__ float blkMax(float v, float* sh) {
    int lane = threadIdx.x & 31, w = threadIdx.x >> 5;
    #pragma unroll
    for (int o = 16; o > 0; o >>= 1) v = fmaxf(v, __shfl_xor_sync(0xffffffffu, v, o));
    if (lane == 0) sh[w] = v;
    __syncthreads();
    float r = sh[0];
    #pragma unroll
    for (int i = 1; i < 8; i++) r = fmaxf(r, sh[i]);
    __syncthreads();
    return r;
}
__device__ __forceinline__ float q8f(float v, float qs) {
    float q = rintf(v * qs);
    return fminf(fmaxf(q, -128.f), 127.f);
}
__device__ __forceinline__ char4 q8x4(float4 v, float qs) {
    char4 r;
    r.x = (int8_t)q8f(v.x, qs); r.y = (int8_t)q8f(v.y, qs);
    r.z = (int8_t)q8f(v.z, qs); r.w = (int8_t)q8f(v.w, qs);
    return r;
}

__device__ __constant__ int c_wn[7] = {589824, 589824, 589824, 4718592, 589824, 2359296, 1179648};

__device__ __forceinline__ const float* pick_w(int id, const float* w0, const float* w1,
    const float* w2, const float* w3, const float* w4, const float* w5, const float* w6) {
    switch (id) { case 0: return w0; case 1: return w1; case 2: return w2; case 3: return w3;
                  case 4: return w4; case 5: return w5; default: return w6; }
}

// ---------- launch 1: weight |w| partial sums (y=0..6) + AdaLN emb (y=7) ----------
__global__ void wabs_emb(const float* w0, const float* w1, const float* w2, const float* w3,
                         const float* w4, const float* w5, const float* w6,
                         const float* __restrict__ c, const float* __restrict__ w_emb,
                         const float* __restrict__ b_emb) {
    int id = blockIdx.y;
    int tid = threadIdx.x;
    if (id == 7) {
        if (blockIdx.x >= 6) return;
        __shared__ float sc[3072];
        for (int idx = tid; idx < 3072; idx += 256) sc[idx] = siluf(c[idx]);
        __syncthreads();
        int n = blockIdx.x * 256 + tid;   // 0..1535
        const float* wr = w_emb + (size_t)n * 768;
        float a0 = b_emb[n], a1 = a0, a2 = a0, a3 = a0;
        for (int k = 0; k < 768; ++k) {
            float wv = wr[k];
            a0 += sc[k] * wv; a1 += sc[768 + k] * wv;
            a2 += sc[1536 + k] * wv; a3 += sc[2304 + k] * wv;
        }
        g_emb[n] = a0; g_emb[1536 + n] = a1; g_emb[3072 + n] = a2; g_emb[4608 + n] = a3;
        return;
    }
    const float* w = pick_w(id, w0, w1, w2, w3, w4, w5, w6);
    int n = c_wn[id];
    __shared__ double sh[256];
    double s = 0.0;
    for (int i = blockIdx.x * 256 + tid; i < n; i += 65536) s += (double)fabsf(w[i]);
    sh[tid] = s; __syncthreads();
    #pragma unroll
    for (int k = 128; k > 0; k >>= 1) { if (tid < k) sh[tid] += sh[tid + k]; __syncthreads(); }
    if (tid == 0) g_part[id * 256 + blockIdx.x] = sh[0];
}

// ---------- launch 2: quantize weights (interleaved layout) + colinv arrays ----------
__global__ void wquant_all(const float* w0, const float* w1, const float* w2, const float* w3,
                           const float* w4, const float* w5, const float* w6) {
    int id = blockIdx.y;
    int tid = threadIdx.x;
    const float* w = pick_w(id, w0, w1, w2, w3, w4, w5, w6);
    int n = c_wn[id];

    __shared__ double sh[256];
    __shared__ float tscs;
    sh[tid] = g_part[id * 256 + tid]; __syncthreads();
    #pragma unroll
    for (int k = 128; k > 0; k >>= 1) { if (tid < k) sh[tid] += sh[tid + k]; __syncthreads(); }
    if (tid == 0) tscs = fmaxf((float)(sh[0] / (double)n), 1e-5f);
    __syncthreads();
    float s = 1.0f / tscs;

    for (int i = blockIdx.x * 256 + tid; i < n; i += 65536) {
        float q = rintf(w[i] * s);
        int8_t qv = (int8_t)fminf(fmaxf(q, -1.f), 1.f);
        int r = i / 768, k = i % 768;
        if (id == 0)      g_wcat[(size_t)(2 * r) * 768 + k] = qv;
        else if (id == 1) g_wcat[(size_t)(2 * r + 1) * 768 + k] = qv;
        else if (id == 2) g_wcat[(size_t)(1536 + r) * 768 + k] = qv;
        else if (id == 3) {
            int dr = (r < 3072) ? (2304 + 2 * r) : (2305 + 2 * (r - 3072));
            g_wcat[(size_t)dr * 768 + k] = qv;
        }
        else if (id == 4) g_wqo[i] = qv;
        else if (id == 5) g_wqd[i] = qv;
        else              g_wqp[i] = qv;
    }

    if (id == 6 && blockIdx.x == 0) {
        __shared__ float tv[7];
        for (int j = 0; j < 7; j++) {
            sh[tid] = g_part[j * 256 + tid]; __syncthreads();
            #pragma unroll
            for (int k = 128; k > 0; k >>= 1) { if (tid < k) sh[tid] += sh[tid + k]; __syncthreads(); }
            if (tid == 0) tv[j] = fmaxf((float)(sh[0] / (double)c_wn[j]), 1e-5f);
            __syncthreads();
        }
        for (int j = tid; j < N1; j += 256) {
            float v;
            if (j < 1536)      v = (j & 1) ? tv[1] : tv[0];
            else if (j < 2304) v = tv[2];
            else               v = tv[3];
            g_cs1[j] = v;
        }
        for (int j = tid; j < 768; j += 256) {
            g_cso[j] = tv[4]; g_csd[j] = tv[5]; g_csp[j] = tv[6];
        }
    }
}

// ---------- launch 3: LN -> adaLN scale -> RMS -> int8 quant (vectorized) ----------
__global__ void norm1_quant(const float* __restrict__ x) {
    __shared__ float sh[8];
    int tok = blockIdx.x, b = tok >> 12, tid = threadIdx.x;
    bool act = tid < 192;
    float4 v = make_float4(0.f, 0.f, 0.f, 0.f);
    if (act) v = ((const float4*)(x + (size_t)tok * 768))[tid];
    float mu = blkSum(v.x + v.y + v.z + v.w, sh) * (1.f / 768.f);
    float4 d;
    d.x = v.x - mu; d.y = v.y - mu; d.z = v.z - mu; d.w = v.w - mu;
    float var = blkSum(act ? (d.x * d.x + d.y * d.y + d.z * d.z + d.w * d.w) : 0.f, sh) * (1.f / 768.f);
    float r1 = 1.f / sqrtf(var + 1e-6f);
    float4 eb = make_float4(0.f, 0.f, 0.f, 0.f);
    if (act) eb = ((const float4*)(g_emb + b * 1536))[tid];
    float4 n;
    n.x = d.x * r1 * (1.f + eb.x); n.y = d.y * r1 * (1.f + eb.y);
    n.z = d.z * r1 * (1.f + eb.z); n.w = d.w * r1 * (1.f + eb.w);
    float ms = blkSum(act ? (n.x * n.x + n.y * n.y + n.z * n.z + n.w * n.w) : 0.f, sh) * (1.f / 768.f);
    float r2 = 1.f / sqrtf(ms + 1e-6f);
    n.x *= r2; n.y *= r2; n.z *= r2; n.w *= r2;
    float lm = act ? fmaxf(fmaxf(fabsf(n.x), fabsf(n.y)), fmaxf(fabsf(n.z), fabsf(n.w))) : 0.f;
    float am = fmaxf(blkMax(lm, sh), 1e-5f);
    float qs = 127.f / am;
    if (act) ((char4*)(g_xq1 + (size_t)tok * 768))[tid] = q8x4(n, qs);
    if (tid == 0) g_ri1[tok] = am * (1.f / 127.f);
}

// ---------- int8 tensor-core GEMM: 128x128 block, 512 threads, 32x32 warp tile ----------
__device__ __forceinline__ void ldsm4(uint32_t* r, uint32_t addr) {
    asm volatile("ldmatrix.sync.aligned.m8n8.x4.shared.b16 {%0,%1,%2,%3}, [%4];\n"
                 : "=r"(r[0]), "=r"(r[1]), "=r"(r[2]), "=r"(r[3]) : "r"(addr));
}
__device__ __forceinline__ void mma_s8(int* c, const uint32_t* a, uint32_t b0, uint32_t b1) {
    asm volatile(
        "mma.sync.aligned.m16n8k32.row.col.s32.s8.s8.s32 "
        "{%0,%1,%2,%3}, {%4,%5,%6,%7}, {%8,%9}, {%0,%1,%2,%3};\n"
        : "+r"(c[0]), "+r"(c[1]), "+r"(c[2]), "+r"(c[3])
        : "r"(a[0]), "r"(a[1]), "r"(a[2]), "r"(a[3]), "r"(b0), "r"(b1));
}
__device__ __forceinline__ void cp16(uint32_t d, const int8_t* s) {
    asm volatile("cp.async.cg.shared.global [%0],[%1],16;\n" :: "r"(d), "l"(s) : "memory");
}

#define A_ST   10240                 // 128 rows * 80B
#define STAGE_BYTES 20480            // A + B
#define NSTG   4

__global__ __launch_bounds__(512, 2)
void gemm_s8(int id, int ldN, int K, const float* __restrict__ xres,
             const float* __restrict__ bias, float* __restrict__ outp) {
    const int8_t* A; const int8_t* Bm; float* C; const float* ri; const float* ci; int mode = 0;
    if (id == 1)      { A = g_xq1; Bm = g_wcat; C = nullptr;  ri = g_ri1; ci = g_cs1; mode = 2; }
    else if (id == 2) { A = g_xq2; Bm = g_wqo;  C = g_cattn;  ri = g_ri2; ci = g_cso; }
    else if (id == 3) { A = g_xq3; Bm = g_wqd;  C = g_cmlp;   ri = g_ri3; ci = g_csd; }
    else              { A = g_xq4; Bm = g_wqp;  C = outp;     ri = g_ri4; ci = g_csp; mode = 1; }

    extern __shared__ int8_t sm[];
    int tid = threadIdx.x, lane = tid & 31, wid = tid >> 5;
    int wm = wid >> 2, wn = wid & 3;           // 4x4 warp grid, warp tile 32x32
    int bm0 = blockIdx.y * 128, bn0 = blockIdx.x * 128;

    // loaders: 4 thr/row x 16B, 128 rows each operand
    const int8_t* gA = A + (size_t)(bm0 + (tid >> 2)) * K + (tid & 3) * 16;
    const int8_t* gB = Bm + (size_t)(bn0 + (tid >> 2)) * K + (tid & 3) * 16;
    uint32_t s0 = (uint32_t)__cvta_generic_to_shared(sm);
    uint32_t wo = (uint32_t)(tid >> 2) * 80 + (tid & 3) * 16;

    int acc[2][4][4];
    #pragma unroll
    for (int a = 0; a < 2; a++)
        #pragma unroll
        for (int b = 0; b < 4; b++)
            #pragma unroll
            for (int r = 0; r < 4; r++) acc[a][b][r] = 0;

    const int KT = K >> 6;

    #pragma unroll
    for (int p = 0; p < 3; p++) {
        uint32_t sb = s0 + p * STAGE_BYTES;
        cp16(sb + wo, gA + p * 64);
        cp16(sb + A_ST + wo, gB + p * 64);
        asm volatile("cp.async.commit_group;\n" ::: "memory");
    }

    uint32_t aOff = (uint32_t)(wm * 32 + (lane & 15)) * 80 + ((lane >> 4) << 4);
    uint32_t bOff = A_ST + (uint32_t)(wn * 32 + (lane & 15)) * 80 + ((lane >> 4) << 4);

    uint32_t stR = 0, stW = 3 * STAGE_BYTES;
    for (int kt = 0; kt < KT; kt++) {
        int rem = KT - 1 - kt;
        if (rem >= 2)      asm volatile("cp.async.wait_group 2;\n" ::: "memory");
        else if (rem == 1) asm volatile("cp.async.wait_group 1;\n" ::: "memory");
        else               asm volatile("cp.async.wait_group 0;\n" ::: "memory");
        __syncthreads();
        if (kt + 3 < KT) {
            uint32_t sb = s0 + stW;
            cp16(sb + wo, gA + (kt + 3) * 64);
            cp16(sb + A_ST + wo, gB + (kt + 3) * 64);
            asm volatile("cp.async.commit_group;\n" ::: "memory");
            stW += STAGE_BYTES; if (stW == NSTG * STAGE_BYTES) stW = 0;
        }
        uint32_t aT = s0 + stR + aOff;
        uint32_t bT = s0 + stR + bOff;
        stR += STAGE_BYTES; if (stR == NSTG * STAGE_BYTES) stR = 0;
        #pragma unroll
        for (int ks = 0; ks < 64; ks += 32) {
            uint32_t af[2][4], bf[2][4];
            ldsm4(af[0], aT + ks);
            ldsm4(af[1], aT + 16 * 80 + ks);
            ldsm4(bf[0], bT + ks);
            ldsm4(bf[1], bT + 16 * 80 + ks);
            #pragma unroll
            for (int fm = 0; fm < 2; ++fm)
                #pragma unroll
                for (int fn = 0; fn < 4; ++fn)
                    mma_s8(acc[fm][fn], af[fm], bf[fn >> 1][fn & 1], bf[fn >> 1][(fn & 1) + 2]);
        }
    }

    // epilogue
    int g = lane >> 2, tg = lane & 3;
    #pragma unroll
    for (int fm = 0; fm < 2; ++fm) {
        int r0 = bm0 + wm * 32 + fm * 16 + g;
        int r1 = r0 + 8;
        float ri0 = ri[r0], ri1 = ri[r1];
        #pragma unroll
        for (int fn = 0; fn < 4; ++fn) {
            int cc = bn0 + wn * 32 + fn * 8 + tg * 2;
            float cv0 = ci[cc], cv1 = ci[cc + 1];
            float v00 = (float)acc[fm][fn][0] * ri0 * cv0;
            float v01 = (float)acc[fm][fn][1] * ri0 * cv1;
            float v10 = (float)acc[fm][fn][2] * ri1 * cv0;
            float v11 = (float)acc[fm][fn][3] * ri1 * cv1;
            if (mode == 2) {
                if (cc < 1536) {                       // (i,f) pair -> u, f
                    int j = cc >> 1;
                    float f0 = sigmf(v01), f1 = sigmf(v11);
                    g_ig[(size_t)r0 * 768 + j] = siluf(v00) * (1.f - f0);
                    g_ig[(size_t)r1 * 768 + j] = siluf(v10) * (1.f - f1);
                    g_fg[(size_t)r0 * 768 + j] = f0;
                    g_fg[(size_t)r1 * 768 + j] = f1;
                } else if (cc < 2304) {                // g -> silu(g)
                    int j = cc - 1536;
                    g_sg[(size_t)r0 * 768 + j] = siluf(v00);
                    g_sg[(size_t)r0 * 768 + j + 1] = siluf(v01);
                    g_sg[(size_t)r1 * 768 + j] = siluf(v10);
                    g_sg[(size_t)r1 * 768 + j + 1] = siluf(v11);
                } else {                               // (gm,y) pair -> m
                    int j = (cc - 2304) >> 1;
                    g_Cm[(size_t)r0 * 3072 + j] = siluf(v00) * v01;
                    g_Cm[(size_t)r1 * 3072 + j] = siluf(v10) * v11;
                }
            } else if (mode == 0) {
                C[(size_t)r0 * ldN + cc] = v00; C[(size_t)r0 * ldN + cc + 1] = v01;
                C[(size_t)r1 * ldN + cc] = v10; C[(size_t)r1 * ldN + cc + 1] = v11;
            } else {
                int b0 = r0 >> 12, b1 = r1 >> 12;
                float gt00 = g_emb[b0 * 1536 + 768 + cc], gt01 = g_emb[b0 * 1536 + 768 + cc + 1];
                float gt10 = g_emb[b1 * 1536 + 768 + cc], gt11 = g_emb[b1 * 1536 + 768 + cc + 1];
                size_t o00 = (size_t)r0 * 768 + cc, o10 = (size_t)r1 * 768 + cc;
                C[o00]     = xres[o00]     + gt00 * (v00 + bias[cc]);
                C[o00 + 1] = xres[o00 + 1] + gt01 * (v01 + bias[cc + 1]);
                C[o10]     = xres[o10]     + gt10 * (v10 + bias[cc]);
                C[o10 + 1] = xres[o10 + 1] + gt11 * (v11 + bias[cc + 1]);
            }
        }
    }
}

// ---------- chunked scan (u already includes (1-f)) ----------
__global__ void scan1() {
    int d = blockIdx.x * 256 + threadIdx.x;
    int c = blockIdx.y, b = blockIdx.z;
    size_t base = ((size_t)(b * 4096 + c * 32)) * 768 + d;
    float h = 0.f, P = 1.f;
    #pragma unroll 8
    for (int t = 0; t < 32; t++) {
        size_t k = base + (size_t)t * 768;
        float f = g_fg[k];
        h = f * h + g_ig[k];
        P *= f;
    }
    size_t idx = (size_t)(b * 128 + c) * 768 + d;
    g_S[idx] = h; g_P[idx] = P;
}
// parallel Hillis-Steele scan over 128 affine (P,S) pairs per (b,d)
__global__ void scan2() {
    __shared__ float sp[128], ss[128];
    int bd = blockIdx.x;           // 0..3071 : b*768 + d
    int b = bd / 768, d = bd % 768;
    int c = threadIdx.x;           // chunk index
    size_t idx = (size_t)(b * 128 + c) * 768 + d;
    sp[c] = g_P[idx]; ss[c] = g_S[idx];
    __syncthreads();
    #pragma unroll
    for (int off = 1; off < 128; off <<= 1) {
        float pc = sp[c], sc = ss[c];
        float pl = 1.f, sl = 0.f;
        if (c >= off) { pl = sp[c - off]; sl = ss[c - off]; }
        __syncthreads();
        sp[c] = pl * pc;
        ss[c] = pc * sl + sc;
        __syncthreads();
    }
    g_Cy[idx] = (c == 0) ? 0.f : ss[c - 1];
}
__global__ void scan3() {
    int d = blockIdx.x * 256 + threadIdx.x;
    int c = blockIdx.y, b = blockIdx.z;
    size_t base = ((size_t)(b * 4096 + c * 32)) * 768 + d;
    float h = g_Cy[(size_t)(b * 128 + c) * 768 + d];
    #pragma unroll 8
    for (int t = 0; t < 32; t++) {
        size_t k = base + (size_t)t * 768;
        h = g_fg[k] * h + g_ig[k];
        g_og[k] = h;
    }
}

// ---------- RMS(o)*w_gn*silu(g) -> RMS -> quant (vectorized) ----------
__global__ void norm2_quant(const float* __restrict__ w_gn) {
    __shared__ float sh[8];
    int tok = blockIdx.x, tid = threadIdx.x;
    bool act = tid < 192;
    float4 o = make_float4(0.f, 0.f, 0.f, 0.f);
    if (act) o = ((const float4*)(g_og + (size_t)tok * 768))[tid];
    float ms = blkSum(act ? (o.x * o.x + o.y * o.y + o.z * o.z + o.w * o.w) : 0.f, sh) * (1.f / 768.f);
    float r1 = 1.f / sqrtf(ms + 1e-6f);
    float4 sg = make_float4(0.f, 0.f, 0.f, 0.f), wg = sg;
    if (act) {
        sg = ((const float4*)(g_sg + (size_t)tok * 768))[tid];
        wg = ((const float4*)w_gn)[tid];
    }
    float4 v;
    v.x = o.x * r1 * wg.x * sg.x; v.y = o.y * r1 * wg.y * sg.y;
    v.z = o.z * r1 * wg.z * sg.z; v.w = o.w * r1 * wg.w * sg.w;
    float ms2 = blkSum(act ? (v.x * v.x + v.y * v.y + v.z * v.z + v.w * v.w) : 0.f, sh) * (1.f / 768.f);
    float r2 = 1.f / sqrtf(ms2 + 1e-6f);
    v.x *= r2; v.y *= r2; v.z *= r2; v.w *= r2;
    float lm = act ? fmaxf(fmaxf(fabsf(v.x), fabsf(v.y)), fmaxf(fabsf(v.z), fabsf(v.w))) : 0.f;
    float am = fmaxf(blkMax(lm, sh), 1e-5f);
    float qs = 127.f / am;
    if (act) ((char4*)(g_xq2 + (size_t)tok * 768))[tid] = q8x4(v, qs);
    if (tid == 0) g_ri2[tok] = am * (1.f / 127.f);
}

// ---------- MLP branch: RMS -> quant (vectorized) ----------
__global__ void mlp_nq() {
    __shared__ float sh[8];
    int tok = blockIdx.x, tid = threadIdx.x;
    const float4* row = (const float4*)(g_Cm + (size_t)tok * 3072);
    float4 mv[3]; float ss = 0.f;
    #pragma unroll
    for (int k = 0; k < 3; k++) {
        mv[k] = row[tid + k * 256];
        ss += mv[k].x * mv[k].x + mv[k].y * mv[k].y + mv[k].z * mv[k].z + mv[k].w * mv[k].w;
    }
    float ms = blkSum(ss, sh) * (1.f / 3072.f);
    float r = 1.f / sqrtf(ms + 1e-6f);
    float am = 0.f;
    #pragma unroll
    for (int k = 0; k < 3; k++)
        am = fmaxf(am, fmaxf(fmaxf(fabsf(mv[k].x), fabsf(mv[k].y)), fmaxf(fabsf(mv[k].z), fabsf(mv[k].w))));
    am = fmaxf(blkMax(am, sh) * r, 1e-5f);
    float qs = 127.f / am;
    char4* dst = (char4*)(g_xq3 + (size_t)tok * 3072);
    #pragma unroll
    for (int k = 0; k < 3; k++) {
        float4 t = make_float4(mv[k].x * r, mv[k].y * r, mv[k].z * r, mv[k].w * r);
        dst[tid + k * 256] = q8x4(t, qs);
    }
    if (tid == 0) g_ri3[tok] = am * (1.f / 127.f);
}

// ---------- concat -> RMS -> quant (vectorized) ----------
__global__ void cat_nq() {
    __shared__ float sh[8];
    int tok = blockIdx.x, tid = threadIdx.x;
    const float4* ca = (const float4*)(g_cattn + (size_t)tok * 768);
    const float4* cm = (const float4*)(g_cmlp + (size_t)tok * 768);
    // element idx j = tid*4 + k*1024 ; j<768 -> cattn, else cmlp[j-768]
    float4 v0 = (tid < 192) ? ca[tid] : cm[tid - 192];
    bool a1 = tid < 128;
    float4 v1 = make_float4(0.f, 0.f, 0.f, 0.f);
    if (a1) v1 = cm[64 + tid];
    float ss = v0.x * v0.x + v0.y * v0.y + v0.z * v0.z + v0.w * v0.w;
    if (a1) ss += v1.x * v1.x + v1.y * v1.y + v1.z * v1.z + v1.w * v1.w;
    float ms = blkSum(ss, sh) * (1.f / 1536.f);
    float r = 1.f / sqrtf(ms + 1e-6f);
    float am = fmaxf(fmaxf(fabsf(v0.x), fabsf(v0.y)), fmaxf(fabsf(v0.z), fabsf(v0.w)));
    if (a1) am = fmaxf(am, fmaxf(fmaxf(fabsf(v1.x), fabsf(v1.y)), fmaxf(fabsf(v1.z), fabsf(v1.w))));
    am = fmaxf(blkMax(am, sh) * r, 1e-5f);
    float qs = 127.f / am;
    char4* dst = (char4*)(g_xq4 + (size_t)tok * 1536);
    float4 t0 = make_float4(v0.x * r, v0.y * r, v0.z * r, v0.w * r);
    dst[tid] = q8x4(t0, qs);
    if (a1) {
        float4 t1 = make_float4(v1.x * r, v1.y * r, v1.z * r, v1.w * r);
        dst[256 + tid] = q8x4(t1, qs);
    }
    if (tid == 0) g_ri4[tok] = am * (1.f / 127.f);
}

// ---------- launch ----------
extern "C" void kernel_launch(void* const* d_in, const int* in_sizes, int n_in,
                              void* d_out, int out_size) {
    const float* x      = (const float*)d_in[0];
    const float* c      = (const float*)d_in[1];
    const float* w_emb  = (const float*)d_in[2];
    const float* b_emb  = (const float*)d_in[3];
    const float* w_i    = (const float*)d_in[4];
    const float* w_f    = (const float*)d_in[5];
    const float* w_g    = (const float*)d_in[6];
    const float* w_gn   = (const float*)d_in[7];
    const float* w_o    = (const float*)d_in[8];
    const float* w_gate = (const float*)d_in[9];
    const float* w_down = (const float*)d_in[10];
    const float* w_proj = (const float*)d_in[11];
    const float* b_proj = (const float*)d_in[12];
    float* out = (float*)d_out;

    const int GSMEM = NSTG * STAGE_BYTES;   // 81920
    cudaFuncSetAttribute(gemm_s8, cudaFuncAttributeMaxDynamicSharedMemorySize, GSMEM);

    wabs_emb<<<dim3(256, 8), 256>>>(w_i, w_f, w_g, w_gate, w_o, w_down, w_proj,
                                    c, w_emb, b_emb);                               // 1
    wquant_all<<<dim3(256, 7), 256>>>(w_i, w_f, w_g, w_gate, w_o, w_down, w_proj);  // 2
    norm1_quant<<<16384, 256>>>(x);                                                 // 3
    gemm_s8<<<dim3(66, 128), 512, GSMEM>>>(1, N1, 768, nullptr, nullptr, nullptr);  // 4 <- ncu
    scan1<<<dim3(3, 128, 4), 256>>>();
    scan2<<<3072, 128>>>();
    scan3<<<dim3(3, 128, 4), 256>>>();
    norm2_quant<<<16384, 256>>>(w_gn);
    gemm_s8<<<dim3(6, 128), 512, GSMEM>>>(2, 768, 768, nullptr, nullptr, nullptr);
    mlp_nq<<<16384, 256>>>();
    gemm_s8<<<dim3(6, 128), 512, GSMEM>>>(3, 768, 3072, nullptr, nullptr, nullptr);
    cat_nq<<<16384, 256>>>();
    gemm_s8<<<dim3(6, 128), 512, GSMEM>>>(4, 768, 1536, x, b_proj, out);
}